// round 2
// baseline (speedup 1.0000x reference)
#include <cuda_runtime.h>
#include <math.h>
#include <float.h>

#define BATCH   16384
#define IN_DIM  362
#define HID     256
#define NSTY    60
#define NOUT    49710
#define D2      724     // 2*IN_DIM

// ---------------- scratch (static device globals; no allocation) ----------------
__device__ float  g_emb[3][BATCH][HID];   // Ti, Bj, Bk  (48 MB)
__device__ int    g_idx[2][BATCH];        // argmin style index (P, N)
__device__ float  g_sscore[2][NSTY];      // precomputed style scores
__device__ float  g_cnorm[2][NSTY];       // ||style col||^2
__device__ double g_acc[4];               // loss1_sum, loss2_sum, loss3_sum, auc_sum

// ---------------- helpers ----------------
__device__ __forceinline__ float sigmoid_f(float x) {
    return 1.0f / (1.0f + expf(-x));
}
// softplus(y) = log(1+e^y), numerically stable
__device__ __forceinline__ float softplus_f(float y) {
    return fmaxf(y, 0.0f) + log1pf(expf(-fabsf(y)));
}

// ---------------- K0: zero accumulators ----------------
__global__ void k_init() {
    if (threadIdx.x < 4) g_acc[threadIdx.x] = 0.0;
}

// ---------------- K1: per-style score table + column norms ----------------
// grid (NSTY, 2), block 256.  z=0 -> P, z=1 -> N
__global__ void k_style(const float* __restrict__ Pm, const float* __restrict__ Nm,
                        const float* __restrict__ Wt, const float* __restrict__ bt,
                        const float* __restrict__ Wb, const float* __restrict__ bb) {
    __shared__ float pc[D2];
    __shared__ float red[256];
    int s = blockIdx.x;
    int z = blockIdx.y;
    const float* M = z ? Nm : Pm;
    for (int d = threadIdx.x; d < D2; d += 256)
        pc[d] = fmaxf(M[d * NSTY + s], 0.0f);
    __syncthreads();

    int h = threadIdx.x;
    float t = bt[h], b = bb[h];
    for (int d = 0; d < IN_DIM; d++) {
        t = fmaf(pc[d],          Wt[d * HID + h], t);
        b = fmaf(pc[IN_DIM + d], Wb[d * HID + h], b);
    }
    float v = sigmoid_f(t) * sigmoid_f(b);
    red[h] = v; __syncthreads();
    for (int off = 128; off > 0; off >>= 1) {
        if (h < off) red[h] += red[h + off];
        __syncthreads();
    }
    if (h == 0) g_sscore[z][s] = red[0];

    float n = 0.0f;
    for (int d = h; d < D2; d += 256) n = fmaf(pc[d], pc[d], n);
    __syncthreads();
    red[h] = n; __syncthreads();
    for (int off = 128; off > 0; off >>= 1) {
        if (h < off) red[h] += red[h + off];
        __syncthreads();
    }
    if (h == 0) g_cnorm[z][s] = red[0];
}

// ---------------- K2: embedding SGEMM + bias + sigmoid ----------------
// grid (2, 128, 3), block 256. z=0: (i,W_top), z=1: (j,W_bot), z=2: (k,W_bot)
#define BM 128
#define BN 128
#define BKK 8
__global__ __launch_bounds__(256) void k_emb(
        const float* __restrict__ fi, const float* __restrict__ fj,
        const float* __restrict__ fk,
        const float* __restrict__ Wt, const float* __restrict__ bt,
        const float* __restrict__ Wb, const float* __restrict__ bb) {
    __shared__ float As[BKK][BM];
    __shared__ float Bs[BKK][BN];
    int z = blockIdx.z;
    const float* A    = (z == 0) ? fi : (z == 1 ? fj : fk);
    const float* B    = (z == 0) ? Wt : Wb;
    const float* bias = (z == 0) ? bt : bb;
    int m0 = blockIdx.y * BM;
    int n0 = blockIdx.x * BN;
    int tid = threadIdx.x;
    int tx = tid % 16, ty = tid / 16;

    float c[8][8];
    #pragma unroll
    for (int i = 0; i < 8; i++)
        #pragma unroll
        for (int j = 0; j < 8; j++) c[i][j] = 0.0f;

    for (int k0 = 0; k0 < IN_DIM; k0 += BKK) {
        #pragma unroll
        for (int i = 0; i < 4; i++) {
            int idx = tid + i * 256;
            int ml = idx >> 3, kk = idx & 7;
            int kg = k0 + kk;
            As[kk][ml] = (kg < IN_DIM) ? A[(size_t)(m0 + ml) * IN_DIM + kg] : 0.0f;
        }
        #pragma unroll
        for (int i = 0; i < 4; i++) {
            int idx = tid + i * 256;
            int kk = idx >> 7, nn = idx & 127;
            int kg = k0 + kk;
            Bs[kk][nn] = (kg < IN_DIM) ? B[kg * HID + n0 + nn] : 0.0f;
        }
        __syncthreads();
        #pragma unroll
        for (int kk = 0; kk < BKK; kk++) {
            float a[8], b[8];
            *(float4*)(a)     = *(const float4*)&As[kk][ty * 8];
            *(float4*)(a + 4) = *(const float4*)&As[kk][ty * 8 + 4];
            *(float4*)(b)     = *(const float4*)&Bs[kk][tx * 8];
            *(float4*)(b + 4) = *(const float4*)&Bs[kk][tx * 8 + 4];
            #pragma unroll
            for (int i = 0; i < 8; i++)
                #pragma unroll
                for (int j = 0; j < 8; j++)
                    c[i][j] = fmaf(a[i], b[j], c[i][j]);
        }
        __syncthreads();
    }
    #pragma unroll
    for (int i = 0; i < 8; i++) {
        int m = m0 + ty * 8 + i;
        #pragma unroll
        for (int j = 0; j < 8; j++) {
            int n = n0 + tx * 8 + j;
            g_emb[z][m][n] = sigmoid_f(c[i][j] + bias[n]);
        }
    }
}

// ---------------- K3: row dot products -> loss1 + auc ----------------
// grid 2048, block 256 (8 warps = 8 rows / block)
__global__ void k_pair() {
    int tid  = threadIdx.x;
    int row  = blockIdx.x * 8 + (tid >> 5);
    int lane = tid & 31;
    const float4* ti = (const float4*)&g_emb[0][row][0];
    const float4* bj = (const float4*)&g_emb[1][row][0];
    const float4* bk = (const float4*)&g_emb[2][row][0];
    float aij = 0.0f, aik = 0.0f;
    #pragma unroll
    for (int q = 0; q < 2; q++) {
        int c4 = lane + q * 32;
        float4 t = ti[c4], j = bj[c4], k = bk[c4];
        aij += t.x * j.x + t.y * j.y + t.z * j.z + t.w * j.w;
        aik += t.x * k.x + t.y * k.y + t.z * k.z + t.w * k.w;
    }
    for (int off = 16; off > 0; off >>= 1) {
        aij += __shfl_xor_sync(0xffffffffu, aij, off);
        aik += __shfl_xor_sync(0xffffffffu, aik, off);
    }
    __shared__ float s1[8], sa[8];
    if (lane == 0) {
        float x = aij - aik;
        s1[tid >> 5] = softplus_f(-x);                  // -log_sigmoid(x)
        sa[tid >> 5] = (aij >= aik) ? 1.0f : 0.0f;      // argmax==0
    }
    __syncthreads();
    if (tid == 0) {
        float l1 = 0.0f, au = 0.0f;
        #pragma unroll
        for (int w = 0; w < 8; w++) { l1 += s1[w]; au += sa[w]; }
        atomicAdd(&g_acc[0], (double)l1);
        atomicAdd(&g_acc[3], (double)au);
    }
}

// ---------------- K4: argmin over styles (drops constant ||outfit||^2) ----------------
// grid (64, 2), block 256, thread = batch row
#define DT 32
__global__ __launch_bounds__(256) void k_argmin(
        const float* __restrict__ fi, const float* __restrict__ fj,
        const float* __restrict__ fk,
        const float* __restrict__ Pm, const float* __restrict__ Nm) {
    __shared__ float fs[256][DT + 1];
    __shared__ float Pt[DT][NSTY];
    int z = blockIdx.y;
    const float* fa = fi;
    const float* fb = z ? fk : fj;
    const float* M  = z ? Nm : Pm;
    int b = blockIdx.x * 256 + threadIdx.x;

    float acc[NSTY];
    #pragma unroll
    for (int s = 0; s < NSTY; s++) acc[s] = 0.0f;

    for (int d0 = 0; d0 < D2; d0 += DT) {
        #pragma unroll
        for (int i = 0; i < DT; i++) {           // 256*DT / 256 = DT iters
            int idx = threadIdx.x + i * 256;
            int r = idx / DT, cc = idx % DT;
            int d = d0 + cc;
            int rb = blockIdx.x * 256 + r;
            float v = 0.0f;
            if (d < D2)
                v = (d < IN_DIM) ? fa[(size_t)rb * IN_DIM + d]
                                 : fb[(size_t)rb * IN_DIM + d - IN_DIM];
            fs[r][cc] = v;
        }
        for (int idx = threadIdx.x; idx < DT * NSTY; idx += 256) {
            int s = idx % NSTY, r = idx / NSTY;
            int d = d0 + r;
            Pt[r][s] = (d < D2) ? fmaxf(M[d * NSTY + s], 0.0f) : 0.0f;
        }
        __syncthreads();
        #pragma unroll 4
        for (int d = 0; d < DT; d++) {
            float f = fs[threadIdx.x][d];
            const float4* p4 = (const float4*)Pt[d];
            #pragma unroll
            for (int s4 = 0; s4 < NSTY / 4; s4++) {
                float4 p = p4[s4];
                acc[s4 * 4 + 0] = fmaf(f, p.x, acc[s4 * 4 + 0]);
                acc[s4 * 4 + 1] = fmaf(f, p.y, acc[s4 * 4 + 1]);
                acc[s4 * 4 + 2] = fmaf(f, p.z, acc[s4 * 4 + 2]);
                acc[s4 * 4 + 3] = fmaf(f, p.w, acc[s4 * 4 + 3]);
            }
        }
        __syncthreads();
    }
    float best = FLT_MAX;
    int bi = 0;
    #pragma unroll
    for (int s = 0; s < NSTY; s++) {
        float v = g_cnorm[z][s] - 2.0f * acc[s];
        if (v < best) { best = v; bi = s; }
    }
    g_idx[z][b] = bi;
}

// ---------------- K5: loss2 from style tables ----------------
// grid 64, block 256
__global__ void k_loss2() {
    int b = blockIdx.x * 256 + threadIdx.x;
    float x = g_sscore[0][g_idx[0][b]] - g_sscore[1][g_idx[1][b]];
    float l = softplus_f(-x);
    for (int off = 16; off > 0; off >>= 1)
        l += __shfl_xor_sync(0xffffffffu, l, off);
    __shared__ float rs[8];
    if ((threadIdx.x & 31) == 0) rs[threadIdx.x >> 5] = l;
    __syncthreads();
    if (threadIdx.x == 0) {
        float t = 0.0f;
        #pragma unroll
        for (int w = 0; w < 8; w++) t += rs[w];
        atomicAdd(&g_acc[1], (double)t);
    }
}

// ---------------- K6: fused loss3 = sum (m - relu(P)@relu(H))^2 ----------------
// grid ((NOUT+63)/64, (D2+63)/64, 2), block 256 (16x16, 4x4 microtile)
#define L3T 64
__global__ __launch_bounds__(256) void k_loss3(
        const float* __restrict__ Pm, const float* __restrict__ Nm,
        const float* __restrict__ H1, const float* __restrict__ H2,
        const float* __restrict__ mpos, const float* __restrict__ mneg) {
    __shared__ float Pst[NSTY][L3T];   // P^T tile: [s][d_local]
    __shared__ float Hs[NSTY][L3T];    // H  tile: [s][o_local]
    int z = blockIdx.z;
    const float* M  = z ? Nm : Pm;
    const float* H  = z ? H2 : H1;
    const float* mm = z ? mneg : mpos;
    int d0 = blockIdx.y * L3T;
    int o0 = blockIdx.x * L3T;
    int tid = threadIdx.x;

    for (int idx = tid; idx < NSTY * L3T; idx += 256) {
        int r = idx % L3T, s = idx / L3T;
        int d = d0 + r;
        Pst[s][r] = (d < D2) ? fmaxf(M[d * NSTY + s], 0.0f) : 0.0f;
    }
    for (int idx = tid; idx < NSTY * L3T; idx += 256) {
        int cc = idx % L3T, s = idx / L3T;
        int o = o0 + cc;
        Hs[s][cc] = (o < NOUT) ? fmaxf(H[(size_t)s * NOUT + o], 0.0f) : 0.0f;
    }
    __syncthreads();

    int tx = tid % 16, ty = tid / 16;
    float c[4][4];
    #pragma unroll
    for (int i = 0; i < 4; i++)
        #pragma unroll
        for (int j = 0; j < 4; j++) c[i][j] = 0.0f;

    #pragma unroll 4
    for (int s = 0; s < NSTY; s++) {
        float4 p = *(const float4*)&Pst[s][ty * 4];
        float4 h = *(const float4*)&Hs[s][tx * 4];
        float pa[4] = {p.x, p.y, p.z, p.w};
        float ha[4] = {h.x, h.y, h.z, h.w};
        #pragma unroll
        for (int i = 0; i < 4; i++)
            #pragma unroll
            for (int j = 0; j < 4; j++)
                c[i][j] = fmaf(pa[i], ha[j], c[i][j]);
    }

    float local = 0.0f;
    #pragma unroll
    for (int i = 0; i < 4; i++) {
        int d = d0 + ty * 4 + i;
        if (d < D2) {
            #pragma unroll
            for (int j = 0; j < 4; j++) {
                int o = o0 + tx * 4 + j;
                if (o < NOUT) {
                    float diff = mm[(size_t)d * NOUT + o] - c[i][j];
                    local = fmaf(diff, diff, local);
                }
            }
        }
    }
    for (int off = 16; off > 0; off >>= 1)
        local += __shfl_xor_sync(0xffffffffu, local, off);
    __shared__ float rs[8];
    if ((tid & 31) == 0) rs[tid >> 5] = local;
    __syncthreads();
    if (tid == 0) {
        float t = 0.0f;
        #pragma unroll
        for (int w = 0; w < 8; w++) t += rs[w];
        atomicAdd(&g_acc[2], (double)t);
    }
}

// ---------------- K7: finalize ----------------
__global__ void k_final(float* __restrict__ out) {
    double l1  = g_acc[0] / (double)BATCH;
    double l2  = g_acc[1] / (double)BATCH;
    double l3  = g_acc[2] / ((double)D2 * (double)NOUT);
    double auc = g_acc[3] / (double)BATCH;
    out[0] = (float)(l1 + l2 + 0.1 * l3);
    out[1] = (float)l1;
    out[2] = (float)l2;
    out[3] = (float)l3;
    out[4] = (float)auc;
}

// ---------------- launch ----------------
extern "C" void kernel_launch(void* const* d_in, const int* in_sizes, int n_in,
                              void* d_out, int out_size) {
    const float* i_f   = (const float*)d_in[0];
    const float* j_f   = (const float*)d_in[1];
    const float* k_f   = (const float*)d_in[2];
    const float* W_top = (const float*)d_in[3];
    const float* b_top = (const float*)d_in[4];
    const float* W_bot = (const float*)d_in[5];
    const float* b_bot = (const float*)d_in[6];
    const float* P_nmf = (const float*)d_in[7];
    const float* N_nmf = (const float*)d_in[8];
    const float* H1    = (const float*)d_in[9];
    const float* H2    = (const float*)d_in[10];
    const float* mpos  = (const float*)d_in[11];
    const float* mneg  = (const float*)d_in[12];
    float* out = (float*)d_out;

    k_init<<<1, 32>>>();
    k_style<<<dim3(NSTY, 2), 256>>>(P_nmf, N_nmf, W_top, b_top, W_bot, b_bot);
    k_emb<<<dim3(2, BATCH / BM, 3), 256>>>(i_f, j_f, k_f, W_top, b_top, W_bot, b_bot);
    k_pair<<<BATCH / 8, 256>>>();
    k_argmin<<<dim3(BATCH / 256, 2), 256>>>(i_f, j_f, k_f, P_nmf, N_nmf);
    k_loss2<<<BATCH / 256, 256>>>();
    k_loss3<<<dim3((NOUT + L3T - 1) / L3T, (D2 + L3T - 1) / L3T, 2), 256>>>(
        P_nmf, N_nmf, H1, H2, mpos, mneg);
    k_final<<<1, 1>>>(out);
}

// round 3
// speedup vs baseline: 1.0688x; 1.0688x over previous
#include <cuda_runtime.h>
#include <math.h>
#include <float.h>

#define BATCH   16384
#define IN_DIM  362
#define HID     256
#define NSTY    60
#define NOUT    49710
#define D2      724     // 2*IN_DIM

// ---------------- scratch (static device globals; no allocation) ----------------
__device__ float  g_emb[3][BATCH][HID];   // Ti, Bj, Bk  (48 MB)
__device__ int    g_idx[2][BATCH];        // argmin style index (P, N)
__device__ float  g_sscore[2][NSTY];      // precomputed style scores
__device__ float  g_cnorm[2][NSTY];       // ||style col||^2
__device__ double g_acc[4];               // loss1_sum, (unused), loss3_sum, auc_sum

// ---------------- helpers ----------------
__device__ __forceinline__ float sigmoid_f(float x) {
    return 1.0f / (1.0f + expf(-x));
}
__device__ __forceinline__ float softplus_f(float y) {   // log(1+e^y)
    return fmaxf(y, 0.0f) + log1pf(expf(-fabsf(y)));
}

// ---------------- K1: per-style score table + column norms (+ acc zeroing) ----------------
// grid (NSTY, 2), block 256.  z=0 -> P, z=1 -> N
__global__ void k_style(const float* __restrict__ Pm, const float* __restrict__ Nm,
                        const float* __restrict__ Wt, const float* __restrict__ bt,
                        const float* __restrict__ Wb, const float* __restrict__ bb) {
    if (blockIdx.x == 0 && blockIdx.y == 0 && threadIdx.x < 4)
        g_acc[threadIdx.x] = 0.0;

    __shared__ float pc[D2];
    __shared__ float red[256];
    int s = blockIdx.x;
    int z = blockIdx.y;
    const float* M = z ? Nm : Pm;
    for (int d = threadIdx.x; d < D2; d += 256)
        pc[d] = fmaxf(M[d * NSTY + s], 0.0f);
    __syncthreads();

    int h = threadIdx.x;
    float t = bt[h], b = bb[h];
    for (int d = 0; d < IN_DIM; d++) {
        t = fmaf(pc[d],          Wt[d * HID + h], t);
        b = fmaf(pc[IN_DIM + d], Wb[d * HID + h], b);
    }
    float v = sigmoid_f(t) * sigmoid_f(b);
    red[h] = v; __syncthreads();
    for (int off = 128; off > 0; off >>= 1) {
        if (h < off) red[h] += red[h + off];
        __syncthreads();
    }
    if (h == 0) g_sscore[z][s] = red[0];

    float n = 0.0f;
    for (int d = h; d < D2; d += 256) n = fmaf(pc[d], pc[d], n);
    __syncthreads();
    red[h] = n; __syncthreads();
    for (int off = 128; off > 0; off >>= 1) {
        if (h < off) red[h] += red[h + off];
        __syncthreads();
    }
    if (h == 0) g_cnorm[z][s] = red[0];
}

// ---------------- K2: embedding SGEMM + bias + sigmoid (double-buffered) ----------------
// grid (2, 128, gz), block 256. z = zbase + blockIdx.z:
//   z=0: (i,W_top), z=1: (j,W_bot), z=2: (k,W_bot)
#define BM 128
#define BN 128
#define BK 16
#define NT ((IN_DIM + BK - 1) / BK)   // 23
__global__ __launch_bounds__(256) void k_emb(
        const float* __restrict__ fi, const float* __restrict__ fj,
        const float* __restrict__ fk,
        const float* __restrict__ Wt, const float* __restrict__ bt,
        const float* __restrict__ Wb, const float* __restrict__ bb,
        int zbase) {
    __shared__ float As[2][BK][BM + 4];
    __shared__ float Bs[2][BK][BN];
    int z = zbase + blockIdx.z;
    const float* A    = (z == 0) ? fi : (z == 1 ? fj : fk);
    const float* B    = (z == 0) ? Wt : Wb;
    const float* bias = (z == 0) ? bt : bb;
    int m0 = blockIdx.y * BM;
    int n0 = blockIdx.x * BN;
    int tid = threadIdx.x;
    int tx = tid % 16, ty = tid / 16;

    // load indices
    int a_ml = tid >> 4;        // +16*i
    int a_kk = tid & 15;
    int b_kk = tid >> 7;        // +2*i
    int b_nn = tid & 127;

    float c[8][8];
    #pragma unroll
    for (int i = 0; i < 8; i++)
        #pragma unroll
        for (int j = 0; j < 8; j++) c[i][j] = 0.0f;

    // prologue: tile 0 into buffer 0 (k < 16 < IN_DIM, no guard needed)
    #pragma unroll
    for (int i = 0; i < 8; i++)
        As[0][a_kk][a_ml + 16 * i] = A[(size_t)(m0 + a_ml + 16 * i) * IN_DIM + a_kk];
    #pragma unroll
    for (int i = 0; i < 8; i++)
        Bs[0][b_kk + 2 * i][b_nn] = B[(size_t)(b_kk + 2 * i) * HID + n0 + b_nn];
    __syncthreads();

    float ra[8], rb[8];
    for (int t = 0; t < NT; t++) {
        int buf = t & 1;
        if (t + 1 < NT) {
            int k0 = (t + 1) * BK;
            #pragma unroll
            for (int i = 0; i < 8; i++) {
                int kg = k0 + a_kk;
                ra[i] = (kg < IN_DIM) ? A[(size_t)(m0 + a_ml + 16 * i) * IN_DIM + kg] : 0.0f;
            }
            #pragma unroll
            for (int i = 0; i < 8; i++) {
                int kg = k0 + b_kk + 2 * i;
                rb[i] = (kg < IN_DIM) ? B[(size_t)kg * HID + n0 + b_nn] : 0.0f;
            }
        }
        #pragma unroll
        for (int kk = 0; kk < BK; kk++) {
            float a[8], b[8];
            *(float4*)(a)     = *(const float4*)&As[buf][kk][ty * 8];
            *(float4*)(a + 4) = *(const float4*)&As[buf][kk][ty * 8 + 4];
            *(float4*)(b)     = *(const float4*)&Bs[buf][kk][tx * 8];
            *(float4*)(b + 4) = *(const float4*)&Bs[buf][kk][tx * 8 + 4];
            #pragma unroll
            for (int i = 0; i < 8; i++)
                #pragma unroll
                for (int j = 0; j < 8; j++)
                    c[i][j] = fmaf(a[i], b[j], c[i][j]);
        }
        if (t + 1 < NT) {
            int nb = buf ^ 1;
            #pragma unroll
            for (int i = 0; i < 8; i++) As[nb][a_kk][a_ml + 16 * i] = ra[i];
            #pragma unroll
            for (int i = 0; i < 8; i++) Bs[nb][b_kk + 2 * i][b_nn] = rb[i];
        }
        __syncthreads();
    }

    float bv[8];
    #pragma unroll
    for (int j = 0; j < 8; j++) bv[j] = bias[n0 + tx * 8 + j];
    #pragma unroll
    for (int i = 0; i < 8; i++) {
        int m = m0 + ty * 8 + i;
        float o[8];
        #pragma unroll
        for (int j = 0; j < 8; j++) o[j] = sigmoid_f(c[i][j] + bv[j]);
        *(float4*)&g_emb[z][m][n0 + tx * 8]     = *(float4*)(o);
        *(float4*)&g_emb[z][m][n0 + tx * 8 + 4] = *(float4*)(o + 4);
    }
}

// ---------------- K3: row dot products -> loss1 + auc ----------------
// grid 2048, block 256 (8 warps = 8 rows / block)
__global__ void k_pair() {
    int tid  = threadIdx.x;
    int row  = blockIdx.x * 8 + (tid >> 5);
    int lane = tid & 31;
    const float4* ti = (const float4*)&g_emb[0][row][0];
    const float4* bj = (const float4*)&g_emb[1][row][0];
    const float4* bk = (const float4*)&g_emb[2][row][0];
    float aij = 0.0f, aik = 0.0f;
    #pragma unroll
    for (int q = 0; q < 2; q++) {
        int c4 = lane + q * 32;
        float4 t = ti[c4], j = bj[c4], k = bk[c4];
        aij += t.x * j.x + t.y * j.y + t.z * j.z + t.w * j.w;
        aik += t.x * k.x + t.y * k.y + t.z * k.z + t.w * k.w;
    }
    for (int off = 16; off > 0; off >>= 1) {
        aij += __shfl_xor_sync(0xffffffffu, aij, off);
        aik += __shfl_xor_sync(0xffffffffu, aik, off);
    }
    __shared__ float s1[8], sa[8];
    if (lane == 0) {
        float x = aij - aik;
        s1[tid >> 5] = softplus_f(-x);
        sa[tid >> 5] = (aij >= aik) ? 1.0f : 0.0f;
    }
    __syncthreads();
    if (tid == 0) {
        float l1 = 0.0f, au = 0.0f;
        #pragma unroll
        for (int w = 0; w < 8; w++) { l1 += s1[w]; au += sa[w]; }
        atomicAdd(&g_acc[0], (double)l1);
        atomicAdd(&g_acc[3], (double)au);
    }
}

// ---------------- K4: argmin over styles ----------------
// grid (64, 2), block 256, thread = batch row
#define DT 32
__global__ __launch_bounds__(256) void k_argmin(
        const float* __restrict__ fi, const float* __restrict__ fj,
        const float* __restrict__ fk,
        const float* __restrict__ Pm, const float* __restrict__ Nm) {
    __shared__ float fs[256][DT + 1];
    __shared__ float Pt[DT][NSTY];
    int z = blockIdx.y;
    const float* fa = fi;
    const float* fb = z ? fk : fj;
    const float* M  = z ? Nm : Pm;
    int b = blockIdx.x * 256 + threadIdx.x;

    float acc[NSTY];
    #pragma unroll
    for (int s = 0; s < NSTY; s++) acc[s] = 0.0f;

    for (int d0 = 0; d0 < D2; d0 += DT) {
        #pragma unroll
        for (int i = 0; i < DT; i++) {
            int idx = threadIdx.x + i * 256;
            int r = idx / DT, cc = idx % DT;
            int d = d0 + cc;
            int rb = blockIdx.x * 256 + r;
            float v = 0.0f;
            if (d < D2)
                v = (d < IN_DIM) ? fa[(size_t)rb * IN_DIM + d]
                                 : fb[(size_t)rb * IN_DIM + d - IN_DIM];
            fs[r][cc] = v;
        }
        for (int idx = threadIdx.x; idx < DT * NSTY; idx += 256) {
            int s = idx % NSTY, r = idx / NSTY;
            int d = d0 + r;
            Pt[r][s] = (d < D2) ? fmaxf(M[d * NSTY + s], 0.0f) : 0.0f;
        }
        __syncthreads();
        #pragma unroll 4
        for (int d = 0; d < DT; d++) {
            float f = fs[threadIdx.x][d];
            const float4* p4 = (const float4*)Pt[d];
            #pragma unroll
            for (int s4 = 0; s4 < NSTY / 4; s4++) {
                float4 p = p4[s4];
                acc[s4 * 4 + 0] = fmaf(f, p.x, acc[s4 * 4 + 0]);
                acc[s4 * 4 + 1] = fmaf(f, p.y, acc[s4 * 4 + 1]);
                acc[s4 * 4 + 2] = fmaf(f, p.z, acc[s4 * 4 + 2]);
                acc[s4 * 4 + 3] = fmaf(f, p.w, acc[s4 * 4 + 3]);
            }
        }
        __syncthreads();
    }
    float best = FLT_MAX;
    int bi = 0;
    #pragma unroll
    for (int s = 0; s < NSTY; s++) {
        float v = g_cnorm[z][s] - 2.0f * acc[s];
        if (v < best) { best = v; bi = s; }
    }
    g_idx[z][b] = bi;
}

// ---------------- K6: fused loss3 = sum (m - relu(P)@relu(H))^2 ----------------
// grid (389, 6, 2), block 256. Tile 128d x 128o, K=60 fully in smem, 8x8 microtile.
#define TD 128
#define TO 128
__global__ __launch_bounds__(256) void k_loss3(
        const float* __restrict__ Pm, const float* __restrict__ Nm,
        const float* __restrict__ H1, const float* __restrict__ H2,
        const float* __restrict__ mpos, const float* __restrict__ mneg) {
    __shared__ float Pst[NSTY][TD + 4];   // [s][d_local]
    __shared__ float Hs[NSTY][TO];        // [s][o_local]
    int z = blockIdx.z;
    const float* M  = z ? Nm : Pm;
    const float* H  = z ? H2 : H1;
    const float* mm = z ? mneg : mpos;
    int d0 = blockIdx.y * TD;
    int o0 = blockIdx.x * TO;
    int tid = threadIdx.x;

    for (int idx = tid; idx < NSTY * TD; idx += 256) {
        int dl = idx & (TD - 1), s = idx >> 7;
        int d = d0 + dl;
        Pst[s][dl] = (d < D2) ? fmaxf(M[d * NSTY + s], 0.0f) : 0.0f;
    }
    for (int idx = tid; idx < NSTY * TO; idx += 256) {
        int ol = idx & (TO - 1), s = idx >> 7;
        int o = o0 + ol;
        Hs[s][ol] = (o < NOUT) ? fmaxf(H[(size_t)s * NOUT + o], 0.0f) : 0.0f;
    }
    __syncthreads();

    int tx = tid % 16, ty = tid / 16;
    float c[8][8];
    #pragma unroll
    for (int i = 0; i < 8; i++)
        #pragma unroll
        for (int j = 0; j < 8; j++) c[i][j] = 0.0f;

    #pragma unroll 10
    for (int s = 0; s < NSTY; s++) {
        float a[8], b[8];
        *(float4*)(a)     = *(const float4*)&Pst[s][ty * 8];
        *(float4*)(a + 4) = *(const float4*)&Pst[s][ty * 8 + 4];
        *(float4*)(b)     = *(const float4*)&Hs[s][tx * 8];
        *(float4*)(b + 4) = *(const float4*)&Hs[s][tx * 8 + 4];
        #pragma unroll
        for (int i = 0; i < 8; i++)
            #pragma unroll
            for (int j = 0; j < 8; j++)
                c[i][j] = fmaf(a[i], b[j], c[i][j]);
    }

    float local = 0.0f;
    #pragma unroll
    for (int i = 0; i < 8; i++) {
        int d = d0 + ty * 8 + i;
        if (d < D2) {
            const float* mrow = mm + (size_t)d * NOUT;
            #pragma unroll
            for (int j = 0; j < 8; j++) {
                int o = o0 + tx * 8 + j;
                if (o < NOUT) {
                    float diff = mrow[o] - c[i][j];
                    local = fmaf(diff, diff, local);
                }
            }
        }
    }
    for (int off = 16; off > 0; off >>= 1)
        local += __shfl_xor_sync(0xffffffffu, local, off);
    __shared__ float rs[8];
    if ((tid & 31) == 0) rs[tid >> 5] = local;
    __syncthreads();
    if (tid == 0) {
        float t = 0.0f;
        #pragma unroll
        for (int w = 0; w < 8; w++) t += rs[w];
        atomicAdd(&g_acc[2], (double)t);
    }
}

// ---------------- K7: loss2 + finalize (single block) ----------------
__global__ void k_final(float* __restrict__ out) {
    __shared__ float s0[NSTY], s1[NSTY];
    __shared__ float red[256];
    int tid = threadIdx.x;
    if (tid < NSTY) { s0[tid] = g_sscore[0][tid]; s1[tid] = g_sscore[1][tid]; }
    __syncthreads();
    float l = 0.0f;
    for (int b = tid; b < BATCH; b += 256) {
        float x = s0[g_idx[0][b]] - s1[g_idx[1][b]];
        l += softplus_f(-x);
    }
    red[tid] = l; __syncthreads();
    for (int off = 128; off > 0; off >>= 1) {
        if (tid < off) red[tid] += red[tid + off];
        __syncthreads();
    }
    if (tid == 0) {
        double l1  = g_acc[0] / (double)BATCH;
        double l2  = (double)red[0] / (double)BATCH;
        double l3  = g_acc[2] / ((double)D2 * (double)NOUT);
        double auc = g_acc[3] / (double)BATCH;
        out[0] = (float)(l1 + l2 + 0.1 * l3);
        out[1] = (float)l1;
        out[2] = (float)l2;
        out[3] = (float)l3;
        out[4] = (float)auc;
    }
}

// ---------------- launch ----------------
extern "C" void kernel_launch(void* const* d_in, const int* in_sizes, int n_in,
                              void* d_out, int out_size) {
    const float* i_f   = (const float*)d_in[0];
    const float* j_f   = (const float*)d_in[1];
    const float* k_f   = (const float*)d_in[2];
    const float* W_top = (const float*)d_in[3];
    const float* b_top = (const float*)d_in[4];
    const float* W_bot = (const float*)d_in[5];
    const float* b_bot = (const float*)d_in[6];
    const float* P_nmf = (const float*)d_in[7];
    const float* N_nmf = (const float*)d_in[8];
    const float* H1    = (const float*)d_in[9];
    const float* H2    = (const float*)d_in[10];
    const float* mpos  = (const float*)d_in[11];
    const float* mneg  = (const float*)d_in[12];
    float* out = (float*)d_out;

    // launch order chosen so ncu (-s 5 -c 1) captures k_loss3 (launch #6)
    k_style<<<dim3(NSTY, 2), 256>>>(P_nmf, N_nmf, W_top, b_top, W_bot, b_bot);      // 1
    k_emb<<<dim3(2, BATCH / BM, 1), 256>>>(i_f, j_f, k_f, W_top, b_top,
                                           W_bot, b_bot, 0);                        // 2 (Ti)
    k_emb<<<dim3(2, BATCH / BM, 2), 256>>>(i_f, j_f, k_f, W_top, b_top,
                                           W_bot, b_bot, 1);                        // 3 (Bj,Bk)
    k_pair<<<BATCH / 8, 256>>>();                                                   // 4
    k_argmin<<<dim3(BATCH / 256, 2), 256>>>(i_f, j_f, k_f, P_nmf, N_nmf);           // 5
    k_loss3<<<dim3((NOUT + TO - 1) / TO, (D2 + TD - 1) / TD, 2), 256>>>(
        P_nmf, N_nmf, H1, H2, mpos, mneg);                                          // 6
    k_final<<<1, 256>>>(out);                                                       // 7
}

// round 4
// speedup vs baseline: 1.4140x; 1.3230x over previous
#include <cuda_runtime.h>
#include <math.h>
#include <float.h>
#include <stdint.h>

#define BATCH   16384
#define IN_DIM  362
#define HID     256
#define NSTY    60
#define NOUT    49710
#define D2      724     // 2*IN_DIM

// ---------------- scratch ----------------
__device__ float  g_emb[3][BATCH][HID];
__device__ int    g_idx[2][BATCH];
__device__ float  g_sscore[2][NSTY];
__device__ float  g_cnorm[2][NSTY];
__device__ double g_acc[4];               // loss1, loss2(unused), loss3, auc

// ---------------- helpers ----------------
__device__ __forceinline__ float sigmoid_f(float x) { return 1.0f / (1.0f + expf(-x)); }
__device__ __forceinline__ float softplus_f(float y) {
    return fmaxf(y, 0.0f) + log1pf(expf(-fabsf(y)));
}
__device__ __forceinline__ uint32_t f2tf32(float x) {
    uint32_t r;
    asm("cvt.rna.tf32.f32 %0, %1;" : "=r"(r) : "f"(x));
    return r;
}
__device__ __forceinline__ void mma_tf32(float* d, const uint32_t* a, const uint32_t* b) {
    asm volatile(
        "mma.sync.aligned.m16n8k8.row.col.f32.tf32.tf32.f32 "
        "{%0,%1,%2,%3}, {%4,%5,%6,%7}, {%8,%9}, {%0,%1,%2,%3};"
        : "+f"(d[0]), "+f"(d[1]), "+f"(d[2]), "+f"(d[3])
        : "r"(a[0]), "r"(a[1]), "r"(a[2]), "r"(a[3]), "r"(b[0]), "r"(b[1]));
}

// ---------------- K0: zero accumulators ----------------
__global__ void k_zero() {
    if (threadIdx.x < 4) g_acc[threadIdx.x] = 0.0;
}

// ---------------- K1: per-style score table + column norms ----------------
__global__ void k_style(const float* __restrict__ Pm, const float* __restrict__ Nm,
                        const float* __restrict__ Wt, const float* __restrict__ bt,
                        const float* __restrict__ Wb, const float* __restrict__ bb) {
    __shared__ float pc[D2];
    __shared__ float red[256];
    int s = blockIdx.x;
    int z = blockIdx.y;
    const float* M = z ? Nm : Pm;
    for (int d = threadIdx.x; d < D2; d += 256)
        pc[d] = fmaxf(M[d * NSTY + s], 0.0f);
    __syncthreads();

    int h = threadIdx.x;
    float t = bt[h], b = bb[h];
    for (int d = 0; d < IN_DIM; d++) {
        t = fmaf(pc[d],          Wt[d * HID + h], t);
        b = fmaf(pc[IN_DIM + d], Wb[d * HID + h], b);
    }
    float v = sigmoid_f(t) * sigmoid_f(b);
    red[h] = v; __syncthreads();
    for (int off = 128; off > 0; off >>= 1) {
        if (h < off) red[h] += red[h + off];
        __syncthreads();
    }
    if (h == 0) g_sscore[z][s] = red[0];

    float n = 0.0f;
    for (int d = h; d < D2; d += 256) n = fmaf(pc[d], pc[d], n);
    __syncthreads();
    red[h] = n; __syncthreads();
    for (int off = 128; off > 0; off >>= 1) {
        if (h < off) red[h] += red[h + off];
        __syncthreads();
    }
    if (h == 0) g_cnorm[z][s] = red[0];
}

// ---------------- K2: loss3 via tf32 tensor MMA ----------------
// grid (389, 6, 2), block 256 (8 warps as 2m x 4n), tile 128d x 128o, K=60 pad 64.
__global__ __launch_bounds__(256) void k_loss3_tc(
        const float* __restrict__ Pm, const float* __restrict__ Nm,
        const float* __restrict__ H1, const float* __restrict__ H2,
        const float* __restrict__ mpos, const float* __restrict__ mneg) {
    extern __shared__ uint32_t sh[];
    uint32_t (*Ps)[68]  = (uint32_t (*)[68])sh;            // [128][68]  A: [d][s]
    uint32_t (*Hs)[136] = (uint32_t (*)[136])(sh + 128 * 68); // [64][136] B: [s][o]

    int z = blockIdx.z;
    const float* M  = z ? Nm : Pm;
    const float* H  = z ? H2 : H1;
    const float* mm = z ? mneg : mpos;
    int d0 = blockIdx.y * 128;
    int o0 = blockIdx.x * 128;
    int tid = threadIdx.x;
    int lane = tid & 31, w = tid >> 5;
    int r = lane >> 2, tg = lane & 3;
    int m0w = (w >> 2) * 64;      // warp row offset in tile
    int n0w = (w & 3) * 32;       // warp col offset in tile

    // load P tile (relu + tf32), pad s in [60,64) with 0
    for (int idx = tid; idx < 128 * 64; idx += 256) {
        int dl = idx >> 6, s = idx & 63;
        int d = d0 + dl;
        float v = (s < NSTY && d < D2) ? fmaxf(M[d * NSTY + s], 0.0f) : 0.0f;
        Ps[dl][s] = f2tf32(v);
    }
    // load H tile (relu + tf32)
    for (int idx = tid; idx < 64 * 128; idx += 256) {
        int s = idx >> 7, ol = idx & 127;
        int o = o0 + ol;
        float v = (s < NSTY && o < NOUT) ? fmaxf(H[(size_t)s * NOUT + o], 0.0f) : 0.0f;
        Hs[s][ol] = f2tf32(v);
    }
    __syncthreads();

    float acc[4][4][4];
    #pragma unroll
    for (int mi = 0; mi < 4; mi++)
        #pragma unroll
        for (int ni = 0; ni < 4; ni++)
            #pragma unroll
            for (int q = 0; q < 4; q++) acc[mi][ni][q] = 0.0f;

    #pragma unroll
    for (int ks = 0; ks < 8; ks++) {
        int kb = ks * 8;
        uint32_t af[4][4], bf[4][2];
        #pragma unroll
        for (int mi = 0; mi < 4; mi++) {
            int mr = m0w + mi * 16;
            af[mi][0] = Ps[mr + r][kb + tg];
            af[mi][1] = Ps[mr + r + 8][kb + tg];
            af[mi][2] = Ps[mr + r][kb + tg + 4];
            af[mi][3] = Ps[mr + r + 8][kb + tg + 4];
        }
        #pragma unroll
        for (int ni = 0; ni < 4; ni++) {
            int nc = n0w + ni * 8 + r;
            bf[ni][0] = Hs[kb + tg][nc];
            bf[ni][1] = Hs[kb + tg + 4][nc];
        }
        #pragma unroll
        for (int mi = 0; mi < 4; mi++)
            #pragma unroll
            for (int ni = 0; ni < 4; ni++)
                mma_tf32(acc[mi][ni], af[mi], bf[ni]);
    }

    // epilogue: (m - PH)^2, guarded
    float local = 0.0f;
    #pragma unroll
    for (int mi = 0; mi < 4; mi++) {
        int dr0 = d0 + m0w + mi * 16 + r;
        int dr1 = dr0 + 8;
        #pragma unroll
        for (int ni = 0; ni < 4; ni++) {
            int o = o0 + n0w + ni * 8 + 2 * tg;
            if (o < NOUT) {
                if (dr0 < D2) {
                    float2 mv = *(const float2*)&mm[(size_t)dr0 * NOUT + o];
                    float e0 = mv.x - acc[mi][ni][0];
                    float e1 = mv.y - acc[mi][ni][1];
                    local = fmaf(e0, e0, local);
                    local = fmaf(e1, e1, local);
                }
                if (dr1 < D2) {
                    float2 mv = *(const float2*)&mm[(size_t)dr1 * NOUT + o];
                    float e2 = mv.x - acc[mi][ni][2];
                    float e3 = mv.y - acc[mi][ni][3];
                    local = fmaf(e2, e2, local);
                    local = fmaf(e3, e3, local);
                }
            }
        }
    }
    for (int off = 16; off > 0; off >>= 1)
        local += __shfl_xor_sync(0xffffffffu, local, off);
    __shared__ float rs[8];
    if (lane == 0) rs[w] = local;
    __syncthreads();
    if (tid == 0) {
        float t = 0.0f;
        #pragma unroll
        for (int q = 0; q < 8; q++) t += rs[q];
        atomicAdd(&g_acc[2], (double)t);
    }
}

// ---------------- K3: argmin over styles (fp32) ----------------
#define DT 32
__global__ __launch_bounds__(256) void k_argmin(
        const float* __restrict__ fi, const float* __restrict__ fj,
        const float* __restrict__ fk,
        const float* __restrict__ Pm, const float* __restrict__ Nm) {
    __shared__ float fs[256][DT + 1];
    __shared__ float Pt[DT][NSTY];
    int z = blockIdx.y;
    const float* fa = fi;
    const float* fb = z ? fk : fj;
    const float* M  = z ? Nm : Pm;
    int b = blockIdx.x * 256 + threadIdx.x;

    float acc[NSTY];
    #pragma unroll
    for (int s = 0; s < NSTY; s++) acc[s] = 0.0f;

    for (int d0 = 0; d0 < D2; d0 += DT) {
        #pragma unroll
        for (int i = 0; i < DT; i++) {
            int idx = threadIdx.x + i * 256;
            int rr = idx / DT, cc = idx % DT;
            int d = d0 + cc;
            int rb = blockIdx.x * 256 + rr;
            float v = 0.0f;
            if (d < D2)
                v = (d < IN_DIM) ? fa[(size_t)rb * IN_DIM + d]
                                 : fb[(size_t)rb * IN_DIM + d - IN_DIM];
            fs[rr][cc] = v;
        }
        for (int idx = threadIdx.x; idx < DT * NSTY; idx += 256) {
            int s = idx % NSTY, rr = idx / NSTY;
            int d = d0 + rr;
            Pt[rr][s] = (d < D2) ? fmaxf(M[d * NSTY + s], 0.0f) : 0.0f;
        }
        __syncthreads();
        #pragma unroll 4
        for (int d = 0; d < DT; d++) {
            float f = fs[threadIdx.x][d];
            const float4* p4 = (const float4*)Pt[d];
            #pragma unroll
            for (int s4 = 0; s4 < NSTY / 4; s4++) {
                float4 p = p4[s4];
                acc[s4 * 4 + 0] = fmaf(f, p.x, acc[s4 * 4 + 0]);
                acc[s4 * 4 + 1] = fmaf(f, p.y, acc[s4 * 4 + 1]);
                acc[s4 * 4 + 2] = fmaf(f, p.z, acc[s4 * 4 + 2]);
                acc[s4 * 4 + 3] = fmaf(f, p.w, acc[s4 * 4 + 3]);
            }
        }
        __syncthreads();
    }
    float best = FLT_MAX;
    int bi = 0;
    #pragma unroll
    for (int s = 0; s < NSTY; s++) {
        float v = g_cnorm[z][s] - 2.0f * acc[s];
        if (v < best) { best = v; bi = s; }
    }
    g_idx[z][b] = bi;
}

// ---------------- K4: embedding GEMM via tf32 MMA + bias + sigmoid ----------------
// grid (2, 128, 3), block 256. Tile 128x128, BK=16 double-buffered, K pad to 368.
#define EBK 16
#define EKT 23
__global__ __launch_bounds__(256) void k_emb_tc(
        const float* __restrict__ fi, const float* __restrict__ fj,
        const float* __restrict__ fk,
        const float* __restrict__ Wt, const float* __restrict__ bt,
        const float* __restrict__ Wb, const float* __restrict__ bb) {
    __shared__ uint32_t As[2][128][20];
    __shared__ uint32_t Bs[2][EBK][136];
    int z = blockIdx.z;
    const float* A    = (z == 0) ? fi : (z == 1 ? fj : fk);
    const float* B    = (z == 0) ? Wt : Wb;
    const float* bias = (z == 0) ? bt : bb;
    int m0 = blockIdx.y * 128;
    int n0 = blockIdx.x * 128;
    int tid = threadIdx.x;
    int lane = tid & 31, w = tid >> 5;
    int r = lane >> 2, tg = lane & 3;
    int m0w = (w >> 2) * 64;
    int n0w = (w & 3) * 32;

    int lm = tid >> 3;           // A row, step 32
    int lk = (tid & 7) * 2;      // A k pair
    int ln = tid & 127;          // B col
    int lkb = tid >> 7;          // B k row, step 2

    float acc[4][4][4];
    #pragma unroll
    for (int mi = 0; mi < 4; mi++)
        #pragma unroll
        for (int ni = 0; ni < 4; ni++)
            #pragma unroll
            for (int q = 0; q < 4; q++) acc[mi][ni][q] = 0.0f;

    // prologue tile 0
    #pragma unroll
    for (int i = 0; i < 4; i++) {
        int m = lm + 32 * i;
        float2 t = *(const float2*)&A[(size_t)(m0 + m) * IN_DIM + lk];
        As[0][m][lk] = f2tf32(t.x); As[0][m][lk + 1] = f2tf32(t.y);
    }
    #pragma unroll
    for (int i = 0; i < 8; i++) {
        int kk = lkb + 2 * i;
        Bs[0][kk][ln] = f2tf32(B[(size_t)kk * HID + n0 + ln]);
    }
    __syncthreads();

    for (int t = 0; t < EKT; t++) {
        int buf = t & 1;
        if (t + 1 < EKT) {
            int k0 = (t + 1) * EBK;
            int nb = buf ^ 1;
            #pragma unroll
            for (int i = 0; i < 4; i++) {
                int m = lm + 32 * i;
                int kg = k0 + lk;
                float v0 = 0.0f, v1 = 0.0f;
                if (kg < IN_DIM) {   // kg even, IN_DIM even -> kg+1 also valid
                    float2 tv = *(const float2*)&A[(size_t)(m0 + m) * IN_DIM + kg];
                    v0 = tv.x; v1 = tv.y;
                }
                As[nb][m][lk] = f2tf32(v0); As[nb][m][lk + 1] = f2tf32(v1);
            }
            #pragma unroll
            for (int i = 0; i < 8; i++) {
                int kk = lkb + 2 * i;
                int kg = k0 + kk;
                float v = (kg < IN_DIM) ? B[(size_t)kg * HID + n0 + ln] : 0.0f;
                Bs[nb][kk][ln] = f2tf32(v);
            }
        }
        #pragma unroll
        for (int ks = 0; ks < 2; ks++) {
            int kb = ks * 8;
            uint32_t af[4][4], bf[4][2];
            #pragma unroll
            for (int mi = 0; mi < 4; mi++) {
                int mr = m0w + mi * 16;
                af[mi][0] = As[buf][mr + r][kb + tg];
                af[mi][1] = As[buf][mr + r + 8][kb + tg];
                af[mi][2] = As[buf][mr + r][kb + tg + 4];
                af[mi][3] = As[buf][mr + r + 8][kb + tg + 4];
            }
            #pragma unroll
            for (int ni = 0; ni < 4; ni++) {
                int nc = n0w + ni * 8 + r;
                bf[ni][0] = Bs[buf][kb + tg][nc];
                bf[ni][1] = Bs[buf][kb + tg + 4][nc];
            }
            #pragma unroll
            for (int mi = 0; mi < 4; mi++)
                #pragma unroll
                for (int ni = 0; ni < 4; ni++)
                    mma_tf32(acc[mi][ni], af[mi], bf[ni]);
        }
        __syncthreads();
    }

    // epilogue: bias + sigmoid + store
    #pragma unroll
    for (int ni = 0; ni < 4; ni++) {
        int col = n0 + n0w + ni * 8 + 2 * tg;
        float b0 = bias[col], b1 = bias[col + 1];
        #pragma unroll
        for (int mi = 0; mi < 4; mi++) {
            int row0 = m0 + m0w + mi * 16 + r;
            float2 o0v, o1v;
            o0v.x = sigmoid_f(acc[mi][ni][0] + b0);
            o0v.y = sigmoid_f(acc[mi][ni][1] + b1);
            o1v.x = sigmoid_f(acc[mi][ni][2] + b0);
            o1v.y = sigmoid_f(acc[mi][ni][3] + b1);
            *(float2*)&g_emb[z][row0][col]     = o0v;
            *(float2*)&g_emb[z][row0 + 8][col] = o1v;
        }
    }
}

// ---------------- K5: row dot products -> loss1 + auc ----------------
__global__ void k_pair() {
    int tid  = threadIdx.x;
    int row  = blockIdx.x * 8 + (tid >> 5);
    int lane = tid & 31;
    const float4* ti = (const float4*)&g_emb[0][row][0];
    const float4* bj = (const float4*)&g_emb[1][row][0];
    const float4* bk = (const float4*)&g_emb[2][row][0];
    float aij = 0.0f, aik = 0.0f;
    #pragma unroll
    for (int q = 0; q < 2; q++) {
        int c4 = lane + q * 32;
        float4 t = ti[c4], j = bj[c4], k = bk[c4];
        aij += t.x * j.x + t.y * j.y + t.z * j.z + t.w * j.w;
        aik += t.x * k.x + t.y * k.y + t.z * k.z + t.w * k.w;
    }
    for (int off = 16; off > 0; off >>= 1) {
        aij += __shfl_xor_sync(0xffffffffu, aij, off);
        aik += __shfl_xor_sync(0xffffffffu, aik, off);
    }
    __shared__ float s1[8], sa[8];
    if (lane == 0) {
        float x = aij - aik;
        s1[tid >> 5] = softplus_f(-x);
        sa[tid >> 5] = (aij >= aik) ? 1.0f : 0.0f;
    }
    __syncthreads();
    if (tid == 0) {
        float l1 = 0.0f, au = 0.0f;
        #pragma unroll
        for (int q = 0; q < 8; q++) { l1 += s1[q]; au += sa[q]; }
        atomicAdd(&g_acc[0], (double)l1);
        atomicAdd(&g_acc[3], (double)au);
    }
}

// ---------------- K6: loss2 + finalize ----------------
__global__ void k_final(float* __restrict__ out) {
    __shared__ float s0[NSTY], s1[NSTY];
    __shared__ float red[256];
    int tid = threadIdx.x;
    if (tid < NSTY) { s0[tid] = g_sscore[0][tid]; s1[tid] = g_sscore[1][tid]; }
    __syncthreads();
    float l = 0.0f;
    for (int b = tid; b < BATCH; b += 256) {
        float x = s0[g_idx[0][b]] - s1[g_idx[1][b]];
        l += softplus_f(-x);
    }
    red[tid] = l; __syncthreads();
    for (int off = 128; off > 0; off >>= 1) {
        if (tid < off) red[tid] += red[tid + off];
        __syncthreads();
    }
    if (tid == 0) {
        double l1  = g_acc[0] / (double)BATCH;
        double l2  = (double)red[0] / (double)BATCH;
        double l3  = g_acc[2] / ((double)D2 * (double)NOUT);
        double auc = g_acc[3] / (double)BATCH;
        out[0] = (float)(l1 + l2 + 0.1 * l3);
        out[1] = (float)l1;
        out[2] = (float)l2;
        out[3] = (float)l3;
        out[4] = (float)auc;
    }
}

// ---------------- launch ----------------
extern "C" void kernel_launch(void* const* d_in, const int* in_sizes, int n_in,
                              void* d_out, int out_size) {
    const float* i_f   = (const float*)d_in[0];
    const float* j_f   = (const float*)d_in[1];
    const float* k_f   = (const float*)d_in[2];
    const float* W_top = (const float*)d_in[3];
    const float* b_top = (const float*)d_in[4];
    const float* W_bot = (const float*)d_in[5];
    const float* b_bot = (const float*)d_in[6];
    const float* P_nmf = (const float*)d_in[7];
    const float* N_nmf = (const float*)d_in[8];
    const float* H1    = (const float*)d_in[9];
    const float* H2    = (const float*)d_in[10];
    const float* mpos  = (const float*)d_in[11];
    const float* mneg  = (const float*)d_in[12];
    float* out = (float*)d_out;

    const int L3_SMEM = (128 * 68 + 64 * 136) * 4;   // 69632 B
    static bool attr_set = false;
    if (!attr_set) {
        cudaFuncSetAttribute(k_loss3_tc, cudaFuncAttributeMaxDynamicSharedMemorySize, L3_SMEM);
        attr_set = true;
    }

    // order: ncu empirically captures launch #4 -> put k_argmin there
    k_zero<<<1, 32>>>();                                                            // 1
    k_style<<<dim3(NSTY, 2), 256>>>(P_nmf, N_nmf, W_top, b_top, W_bot, b_bot);      // 2
    k_loss3_tc<<<dim3((NOUT + 127) / 128, (D2 + 127) / 128, 2), 256, L3_SMEM>>>(
        P_nmf, N_nmf, H1, H2, mpos, mneg);                                          // 3
    k_argmin<<<dim3(BATCH / 256, 2), 256>>>(i_f, j_f, k_f, P_nmf, N_nmf);           // 4
    k_emb_tc<<<dim3(2, BATCH / 128, 3), 256>>>(i_f, j_f, k_f, W_top, b_top,
                                               W_bot, b_bot);                       // 5
    k_pair<<<BATCH / 8, 256>>>();                                                   // 6
    k_final<<<1, 256>>>(out);                                                       // 7
}

// round 5
// speedup vs baseline: 1.4915x; 1.0548x over previous
#include <cuda_runtime.h>
#include <math.h>
#include <float.h>
#include <stdint.h>

#define BATCH   16384
#define IN_DIM  362
#define HID     256
#define NSTY    60
#define NOUT    49710
#define D2      724     // 2*IN_DIM

// ---------------- scratch ----------------
__device__ float  g_emb[3][BATCH][HID];
__device__ int    g_idx[2][BATCH];
__device__ float  g_sscore[2][NSTY];
__device__ float  g_cnorm[2][NSTY];
__device__ double g_acc[4];               // loss1, (unused), loss3, auc

// ---------------- helpers ----------------
__device__ __forceinline__ float sigmoid_f(float x) { return 1.0f / (1.0f + expf(-x)); }
__device__ __forceinline__ float softplus_f(float y) {
    return fmaxf(y, 0.0f) + log1pf(expf(-fabsf(y)));
}
__device__ __forceinline__ uint32_t f2tf32(float x) {
    uint32_t r;
    asm("cvt.rna.tf32.f32 %0, %1;" : "=r"(r) : "f"(x));
    return r;
}
__device__ __forceinline__ void mma_tf32(float* d, const uint32_t* a, const uint32_t* b) {
    asm volatile(
        "mma.sync.aligned.m16n8k8.row.col.f32.tf32.tf32.f32 "
        "{%0,%1,%2,%3}, {%4,%5,%6,%7}, {%8,%9}, {%0,%1,%2,%3};"
        : "+f"(d[0]), "+f"(d[1]), "+f"(d[2]), "+f"(d[3])
        : "r"(a[0]), "r"(a[1]), "r"(a[2]), "r"(a[3]), "r"(b[0]), "r"(b[1]));
}

// ---------------- K0: zero accumulators ----------------
__global__ void k_zero() {
    if (threadIdx.x < 4) g_acc[threadIdx.x] = 0.0;
}

// ---------------- K1: per-style score table + column norms ----------------
__global__ void k_style(const float* __restrict__ Pm, const float* __restrict__ Nm,
                        const float* __restrict__ Wt, const float* __restrict__ bt,
                        const float* __restrict__ Wb, const float* __restrict__ bb) {
    __shared__ float pc[D2];
    __shared__ float red[256];
    int s = blockIdx.x;
    int z = blockIdx.y;
    const float* M = z ? Nm : Pm;
    for (int d = threadIdx.x; d < D2; d += 256)
        pc[d] = fmaxf(M[d * NSTY + s], 0.0f);
    __syncthreads();

    int h = threadIdx.x;
    float t = bt[h], b = bb[h];
    for (int d = 0; d < IN_DIM; d++) {
        t = fmaf(pc[d],          Wt[d * HID + h], t);
        b = fmaf(pc[IN_DIM + d], Wb[d * HID + h], b);
    }
    float v = sigmoid_f(t) * sigmoid_f(b);
    red[h] = v; __syncthreads();
    for (int off = 128; off > 0; off >>= 1) {
        if (h < off) red[h] += red[h + off];
        __syncthreads();
    }
    if (h == 0) g_sscore[z][s] = red[0];

    float n = 0.0f;
    for (int d = h; d < D2; d += 256) n = fmaf(pc[d], pc[d], n);
    __syncthreads();
    red[h] = n; __syncthreads();
    for (int off = 128; off > 0; off >>= 1) {
        if (h < off) red[h] += red[h + off];
        __syncthreads();
    }
    if (h == 0) g_cnorm[z][s] = red[0];
}

// ---------------- K2: argmin via split-tf32 tensor MMA ----------------
// C[b,s] = F[b,:] . relu(S[:,s]) with 3xTF32 (fp32-equivalent precision).
// grid (128, 2), block 256 (8 warps = 4m x 2n), tile 128 rows x 64 styles.
#define AKC 32                       // k chunk
#define ANC 23                       // ceil(724/32)
// smem word layout: Fh[128][36], Fl[128][36], Sh[32][68], Sl[32][68]
#define OFF_FH 0
#define OFF_FL (128 * 36)
#define OFF_SH (2 * 128 * 36)
#define OFF_SL (2 * 128 * 36 + 32 * 68)
#define ARG_SMEM ((2 * 128 * 36 + 2 * 32 * 68) * 4)
__global__ __launch_bounds__(256) void k_argmin_tc(
        const float* __restrict__ fi, const float* __restrict__ fj,
        const float* __restrict__ fk,
        const float* __restrict__ Pm, const float* __restrict__ Nm) {
    extern __shared__ uint32_t sb[];
    uint32_t (*Fh)[36] = (uint32_t (*)[36])(sb + OFF_FH);
    uint32_t (*Fl)[36] = (uint32_t (*)[36])(sb + OFF_FL);
    uint32_t (*Sh)[68] = (uint32_t (*)[68])(sb + OFF_SH);
    uint32_t (*Sl)[68] = (uint32_t (*)[68])(sb + OFF_SL);

    int z = blockIdx.y;
    const float* fa = fi;
    const float* fb = z ? fk : fj;
    const float* M  = z ? Nm : Pm;
    int b0 = blockIdx.x * 128;
    int tid = threadIdx.x;
    int lane = tid & 31, w = tid >> 5;
    int r = lane >> 2, tg = lane & 3;
    int wm = (w >> 1) * 32;       // warp row offset (4 warps in m)
    int wn = (w & 1) * 32;        // warp col offset (2 warps in n)

    float acc[2][4][4];
    #pragma unroll
    for (int mi = 0; mi < 2; mi++)
        #pragma unroll
        for (int ni = 0; ni < 4; ni++)
            #pragma unroll
            for (int q = 0; q < 4; q++) acc[mi][ni][q] = 0.0f;

    for (int c = 0; c < ANC; c++) {
        int k0 = c * AKC;
        // load F chunk: 128 rows x 32 k (coalesced in k)
        #pragma unroll
        for (int i = 0; i < 16; i++) {
            int idx = tid + i * 256;
            int row = idx >> 5, kk = idx & 31;
            int d = k0 + kk;
            float v = 0.0f;
            if (d < D2)
                v = (d < IN_DIM) ? fa[(size_t)(b0 + row) * IN_DIM + d]
                                 : fb[(size_t)(b0 + row) * IN_DIM + d - IN_DIM];
            uint32_t hi = f2tf32(v);
            Fh[row][kk] = hi;
            Fl[row][kk] = f2tf32(v - __uint_as_float(hi));
        }
        // load S chunk: 32 k x 64 styles (pad s>=60 and d>=724 with 0)
        #pragma unroll
        for (int i = 0; i < 8; i++) {
            int idx = tid + i * 256;
            int kk = idx >> 6, s = idx & 63;
            int d = k0 + kk;
            float v = (s < NSTY && d < D2) ? fmaxf(M[d * NSTY + s], 0.0f) : 0.0f;
            uint32_t hi = f2tf32(v);
            Sh[kk][s] = hi;
            Sl[kk][s] = f2tf32(v - __uint_as_float(hi));
        }
        __syncthreads();
        #pragma unroll
        for (int ks = 0; ks < 4; ks++) {
            int kb = ks * 8;
            uint32_t ah[2][4], al[2][4], bh[4][2], bl[4][2];
            #pragma unroll
            for (int mi = 0; mi < 2; mi++) {
                int mr = wm + mi * 16;
                ah[mi][0] = Fh[mr + r][kb + tg];
                ah[mi][1] = Fh[mr + r + 8][kb + tg];
                ah[mi][2] = Fh[mr + r][kb + tg + 4];
                ah[mi][3] = Fh[mr + r + 8][kb + tg + 4];
                al[mi][0] = Fl[mr + r][kb + tg];
                al[mi][1] = Fl[mr + r + 8][kb + tg];
                al[mi][2] = Fl[mr + r][kb + tg + 4];
                al[mi][3] = Fl[mr + r + 8][kb + tg + 4];
            }
            #pragma unroll
            for (int ni = 0; ni < 4; ni++) {
                int nc = wn + ni * 8 + r;
                bh[ni][0] = Sh[kb + tg][nc];
                bh[ni][1] = Sh[kb + tg + 4][nc];
                bl[ni][0] = Sl[kb + tg][nc];
                bl[ni][1] = Sl[kb + tg + 4][nc];
            }
            #pragma unroll
            for (int mi = 0; mi < 2; mi++)
                #pragma unroll
                for (int ni = 0; ni < 4; ni++) {
                    mma_tf32(acc[mi][ni], ah[mi], bh[ni]);
                    mma_tf32(acc[mi][ni], ah[mi], bl[ni]);
                    mma_tf32(acc[mi][ni], al[mi], bh[ni]);
                }
        }
        __syncthreads();
    }

    // write C to smem (overlay on F region), then per-row argmin
    float (*Cs)[68] = (float (*)[68])(sb + OFF_FH);
    #pragma unroll
    for (int mi = 0; mi < 2; mi++) {
        int mr = wm + mi * 16;
        #pragma unroll
        for (int ni = 0; ni < 4; ni++) {
            int nc = wn + ni * 8 + 2 * tg;
            Cs[mr + r][nc]         = acc[mi][ni][0];
            Cs[mr + r][nc + 1]     = acc[mi][ni][1];
            Cs[mr + r + 8][nc]     = acc[mi][ni][2];
            Cs[mr + r + 8][nc + 1] = acc[mi][ni][3];
        }
    }
    __syncthreads();
    if (tid < 128) {
        float best = FLT_MAX;
        int bi = 0;
        const float* crow = Cs[tid];
        #pragma unroll
        for (int s = 0; s < NSTY; s++) {
            float v = g_cnorm[z][s] - 2.0f * crow[s];
            if (v < best) { best = v; bi = s; }
        }
        g_idx[z][b0 + tid] = bi;
    }
}

// ---------------- K3: loss3 via tf32 tensor MMA ----------------
// grid (389, 6, 2), block 256 (8 warps as 2m x 4n), tile 128d x 128o, K=60 pad 64.
__global__ __launch_bounds__(256) void k_loss3_tc(
        const float* __restrict__ Pm, const float* __restrict__ Nm,
        const float* __restrict__ H1, const float* __restrict__ H2,
        const float* __restrict__ mpos, const float* __restrict__ mneg) {
    extern __shared__ uint32_t sh[];
    uint32_t (*Ps)[68]  = (uint32_t (*)[68])sh;               // [128][68]
    uint32_t (*Hs)[136] = (uint32_t (*)[136])(sh + 128 * 68); // [64][136]

    int z = blockIdx.z;
    const float* M  = z ? Nm : Pm;
    const float* H  = z ? H2 : H1;
    const float* mm = z ? mneg : mpos;
    int d0 = blockIdx.y * 128;
    int o0 = blockIdx.x * 128;
    int tid = threadIdx.x;
    int lane = tid & 31, w = tid >> 5;
    int r = lane >> 2, tg = lane & 3;
    int m0w = (w >> 2) * 64;
    int n0w = (w & 3) * 32;

    for (int idx = tid; idx < 128 * 64; idx += 256) {
        int dl = idx >> 6, s = idx & 63;
        int d = d0 + dl;
        float v = (s < NSTY && d < D2) ? fmaxf(M[d * NSTY + s], 0.0f) : 0.0f;
        Ps[dl][s] = f2tf32(v);
    }
    for (int idx = tid; idx < 64 * 128; idx += 256) {
        int s = idx >> 7, ol = idx & 127;
        int o = o0 + ol;
        float v = (s < NSTY && o < NOUT) ? fmaxf(H[(size_t)s * NOUT + o], 0.0f) : 0.0f;
        Hs[s][ol] = f2tf32(v);
    }
    __syncthreads();

    float acc[4][4][4];
    #pragma unroll
    for (int mi = 0; mi < 4; mi++)
        #pragma unroll
        for (int ni = 0; ni < 4; ni++)
            #pragma unroll
            for (int q = 0; q < 4; q++) acc[mi][ni][q] = 0.0f;

    #pragma unroll
    for (int ks = 0; ks < 8; ks++) {
        int kb = ks * 8;
        uint32_t af[4][4], bf[4][2];
        #pragma unroll
        for (int mi = 0; mi < 4; mi++) {
            int mr = m0w + mi * 16;
            af[mi][0] = Ps[mr + r][kb + tg];
            af[mi][1] = Ps[mr + r + 8][kb + tg];
            af[mi][2] = Ps[mr + r][kb + tg + 4];
            af[mi][3] = Ps[mr + r + 8][kb + tg + 4];
        }
        #pragma unroll
        for (int ni = 0; ni < 4; ni++) {
            int nc = n0w + ni * 8 + r;
            bf[ni][0] = Hs[kb + tg][nc];
            bf[ni][1] = Hs[kb + tg + 4][nc];
        }
        #pragma unroll
        for (int mi = 0; mi < 4; mi++)
            #pragma unroll
            for (int ni = 0; ni < 4; ni++)
                mma_tf32(acc[mi][ni], af[mi], bf[ni]);
    }

    float local = 0.0f;
    #pragma unroll
    for (int mi = 0; mi < 4; mi++) {
        int dr0 = d0 + m0w + mi * 16 + r;
        int dr1 = dr0 + 8;
        #pragma unroll
        for (int ni = 0; ni < 4; ni++) {
            int o = o0 + n0w + ni * 8 + 2 * tg;
            if (o < NOUT) {
                if (dr0 < D2) {
                    float2 mv = *(const float2*)&mm[(size_t)dr0 * NOUT + o];
                    float e0 = mv.x - acc[mi][ni][0];
                    float e1 = mv.y - acc[mi][ni][1];
                    local = fmaf(e0, e0, local);
                    local = fmaf(e1, e1, local);
                }
                if (dr1 < D2) {
                    float2 mv = *(const float2*)&mm[(size_t)dr1 * NOUT + o];
                    float e2 = mv.x - acc[mi][ni][2];
                    float e3 = mv.y - acc[mi][ni][3];
                    local = fmaf(e2, e2, local);
                    local = fmaf(e3, e3, local);
                }
            }
        }
    }
    for (int off = 16; off > 0; off >>= 1)
        local += __shfl_xor_sync(0xffffffffu, local, off);
    __shared__ float rs[8];
    if (lane == 0) rs[w] = local;
    __syncthreads();
    if (tid == 0) {
        float t = 0.0f;
        #pragma unroll
        for (int q = 0; q < 8; q++) t += rs[q];
        atomicAdd(&g_acc[2], (double)t);
    }
}

// ---------------- K4: embedding GEMM via tf32 MMA + bias + sigmoid ----------------
#define EBK 16
#define EKT 23
__global__ __launch_bounds__(256) void k_emb_tc(
        const float* __restrict__ fi, const float* __restrict__ fj,
        const float* __restrict__ fk,
        const float* __restrict__ Wt, const float* __restrict__ bt,
        const float* __restrict__ Wb, const float* __restrict__ bb) {
    __shared__ uint32_t As[2][128][20];
    __shared__ uint32_t Bs[2][EBK][136];
    int z = blockIdx.z;
    const float* A    = (z == 0) ? fi : (z == 1 ? fj : fk);
    const float* B    = (z == 0) ? Wt : Wb;
    const float* bias = (z == 0) ? bt : bb;
    int m0 = blockIdx.y * 128;
    int n0 = blockIdx.x * 128;
    int tid = threadIdx.x;
    int lane = tid & 31, w = tid >> 5;
    int r = lane >> 2, tg = lane & 3;
    int m0w = (w >> 2) * 64;
    int n0w = (w & 3) * 32;

    int lm = tid >> 3;
    int lk = (tid & 7) * 2;
    int ln = tid & 127;
    int lkb = tid >> 7;

    float acc[4][4][4];
    #pragma unroll
    for (int mi = 0; mi < 4; mi++)
        #pragma unroll
        for (int ni = 0; ni < 4; ni++)
            #pragma unroll
            for (int q = 0; q < 4; q++) acc[mi][ni][q] = 0.0f;

    #pragma unroll
    for (int i = 0; i < 4; i++) {
        int m = lm + 32 * i;
        float2 t = *(const float2*)&A[(size_t)(m0 + m) * IN_DIM + lk];
        As[0][m][lk] = f2tf32(t.x); As[0][m][lk + 1] = f2tf32(t.y);
    }
    #pragma unroll
    for (int i = 0; i < 8; i++) {
        int kk = lkb + 2 * i;
        Bs[0][kk][ln] = f2tf32(B[(size_t)kk * HID + n0 + ln]);
    }
    __syncthreads();

    for (int t = 0; t < EKT; t++) {
        int buf = t & 1;
        if (t + 1 < EKT) {
            int k0 = (t + 1) * EBK;
            int nb = buf ^ 1;
            #pragma unroll
            for (int i = 0; i < 4; i++) {
                int m = lm + 32 * i;
                int kg = k0 + lk;
                float v0 = 0.0f, v1 = 0.0f;
                if (kg < IN_DIM) {
                    float2 tv = *(const float2*)&A[(size_t)(m0 + m) * IN_DIM + kg];
                    v0 = tv.x; v1 = tv.y;
                }
                As[nb][m][lk] = f2tf32(v0); As[nb][m][lk + 1] = f2tf32(v1);
            }
            #pragma unroll
            for (int i = 0; i < 8; i++) {
                int kk = lkb + 2 * i;
                int kg = k0 + kk;
                float v = (kg < IN_DIM) ? B[(size_t)kg * HID + n0 + ln] : 0.0f;
                Bs[nb][kk][ln] = f2tf32(v);
            }
        }
        #pragma unroll
        for (int ks = 0; ks < 2; ks++) {
            int kb = ks * 8;
            uint32_t af[4][4], bf[4][2];
            #pragma unroll
            for (int mi = 0; mi < 4; mi++) {
                int mr = m0w + mi * 16;
                af[mi][0] = As[buf][mr + r][kb + tg];
                af[mi][1] = As[buf][mr + r + 8][kb + tg];
                af[mi][2] = As[buf][mr + r][kb + tg + 4];
                af[mi][3] = As[buf][mr + r + 8][kb + tg + 4];
            }
            #pragma unroll
            for (int ni = 0; ni < 4; ni++) {
                int nc = n0w + ni * 8 + r;
                bf[ni][0] = Bs[buf][kb + tg][nc];
                bf[ni][1] = Bs[buf][kb + tg + 4][nc];
            }
            #pragma unroll
            for (int mi = 0; mi < 4; mi++)
                #pragma unroll
                for (int ni = 0; ni < 4; ni++)
                    mma_tf32(acc[mi][ni], af[mi], bf[ni]);
        }
        __syncthreads();
    }

    #pragma unroll
    for (int ni = 0; ni < 4; ni++) {
        int col = n0 + n0w + ni * 8 + 2 * tg;
        float b0 = bias[col], b1 = bias[col + 1];
        #pragma unroll
        for (int mi = 0; mi < 4; mi++) {
            int row0 = m0 + m0w + mi * 16 + r;
            float2 o0v, o1v;
            o0v.x = sigmoid_f(acc[mi][ni][0] + b0);
            o0v.y = sigmoid_f(acc[mi][ni][1] + b1);
            o1v.x = sigmoid_f(acc[mi][ni][2] + b0);
            o1v.y = sigmoid_f(acc[mi][ni][3] + b1);
            *(float2*)&g_emb[z][row0][col]     = o0v;
            *(float2*)&g_emb[z][row0 + 8][col] = o1v;
        }
    }
}

// ---------------- K5: row dot products -> loss1 + auc ----------------
__global__ void k_pair() {
    int tid  = threadIdx.x;
    int row  = blockIdx.x * 8 + (tid >> 5);
    int lane = tid & 31;
    const float4* ti = (const float4*)&g_emb[0][row][0];
    const float4* bj = (const float4*)&g_emb[1][row][0];
    const float4* bk = (const float4*)&g_emb[2][row][0];
    float aij = 0.0f, aik = 0.0f;
    #pragma unroll
    for (int q = 0; q < 2; q++) {
        int c4 = lane + q * 32;
        float4 t = ti[c4], j = bj[c4], k = bk[c4];
        aij += t.x * j.x + t.y * j.y + t.z * j.z + t.w * j.w;
        aik += t.x * k.x + t.y * k.y + t.z * k.z + t.w * k.w;
    }
    for (int off = 16; off > 0; off >>= 1) {
        aij += __shfl_xor_sync(0xffffffffu, aij, off);
        aik += __shfl_xor_sync(0xffffffffu, aik, off);
    }
    __shared__ float s1[8], sa[8];
    if (lane == 0) {
        float x = aij - aik;
        s1[tid >> 5] = softplus_f(-x);
        sa[tid >> 5] = (aij >= aik) ? 1.0f : 0.0f;
    }
    __syncthreads();
    if (tid == 0) {
        float l1 = 0.0f, au = 0.0f;
        #pragma unroll
        for (int q = 0; q < 8; q++) { l1 += s1[q]; au += sa[q]; }
        atomicAdd(&g_acc[0], (double)l1);
        atomicAdd(&g_acc[3], (double)au);
    }
}

// ---------------- K6: loss2 + finalize ----------------
__global__ void k_final(float* __restrict__ out) {
    __shared__ float s0[NSTY], s1[NSTY];
    __shared__ float red[256];
    int tid = threadIdx.x;
    if (tid < NSTY) { s0[tid] = g_sscore[0][tid]; s1[tid] = g_sscore[1][tid]; }
    __syncthreads();
    float l = 0.0f;
    for (int b = tid; b < BATCH; b += 256) {
        float x = s0[g_idx[0][b]] - s1[g_idx[1][b]];
        l += softplus_f(-x);
    }
    red[tid] = l; __syncthreads();
    for (int off = 128; off > 0; off >>= 1) {
        if (tid < off) red[tid] += red[tid + off];
        __syncthreads();
    }
    if (tid == 0) {
        double l1  = g_acc[0] / (double)BATCH;
        double l2  = (double)red[0] / (double)BATCH;
        double l3  = g_acc[2] / ((double)D2 * (double)NOUT);
        double auc = g_acc[3] / (double)BATCH;
        out[0] = (float)(l1 + l2 + 0.1 * l3);
        out[1] = (float)l1;
        out[2] = (float)l2;
        out[3] = (float)l3;
        out[4] = (float)auc;
    }
}

// ---------------- launch ----------------
extern "C" void kernel_launch(void* const* d_in, const int* in_sizes, int n_in,
                              void* d_out, int out_size) {
    const float* i_f   = (const float*)d_in[0];
    const float* j_f   = (const float*)d_in[1];
    const float* k_f   = (const float*)d_in[2];
    const float* W_top = (const float*)d_in[3];
    const float* b_top = (const float*)d_in[4];
    const float* W_bot = (const float*)d_in[5];
    const float* b_bot = (const float*)d_in[6];
    const float* P_nmf = (const float*)d_in[7];
    const float* N_nmf = (const float*)d_in[8];
    const float* H1    = (const float*)d_in[9];
    const float* H2    = (const float*)d_in[10];
    const float* mpos  = (const float*)d_in[11];
    const float* mneg  = (const float*)d_in[12];
    float* out = (float*)d_out;

    const int L3_SMEM = (128 * 68 + 64 * 136) * 4;   // 69632 B
    static bool attr_set = false;
    if (!attr_set) {
        cudaFuncSetAttribute(k_loss3_tc, cudaFuncAttributeMaxDynamicSharedMemorySize, L3_SMEM);
        cudaFuncSetAttribute(k_argmin_tc, cudaFuncAttributeMaxDynamicSharedMemorySize, ARG_SMEM);
        attr_set = true;
    }

    // slot #4 (ncu capture) = k_loss3_tc
    k_zero<<<1, 32>>>();                                                            // 1
    k_style<<<dim3(NSTY, 2), 256>>>(P_nmf, N_nmf, W_top, b_top, W_bot, b_bot);      // 2
    k_argmin_tc<<<dim3(BATCH / 128, 2), 256, ARG_SMEM>>>(i_f, j_f, k_f,
                                                         P_nmf, N_nmf);             // 3
    k_loss3_tc<<<dim3((NOUT + 127) / 128, (D2 + 127) / 128, 2), 256, L3_SMEM>>>(
        P_nmf, N_nmf, H1, H2, mpos, mneg);                                          // 4
    k_emb_tc<<<dim3(2, BATCH / 128, 3), 256>>>(i_f, j_f, k_f, W_top, b_top,
                                               W_bot, b_bot);                       // 5
    k_pair<<<BATCH / 8, 256>>>();                                                   // 6
    k_final<<<1, 256>>>(out);                                                       // 7
}